// round 13
// baseline (speedup 1.0000x reference)
#include <cuda_runtime.h>
#include <cuda_bf16.h>
#include <mma.h>
#include <cstdint>

#define NPTS   80000
#define NDPTS  10000
#define KOFF   27

typedef unsigned long long ull;
typedef unsigned int u32;

using namespace nvcuda;

// ---------------- packed fp32x2 helpers ----------------
__device__ __forceinline__ ull ffma2(ull a, ull b, ull c) {
    ull d;
    asm("fma.rn.f32x2 %0, %1, %2, %3;" : "=l"(d) : "l"(a), "l"(b), "l"(c));
    return d;
}
__device__ __forceinline__ ull pack2(float v) {
    ull d;
    asm("mov.b64 %0, {%1, %1};" : "=l"(d) : "f"(v));
    return d;
}
__device__ __forceinline__ ull packf2(float a, float b) {
    ull d;
    asm("mov.b64 %0, {%1, %2};" : "=l"(d) : "f"(a), "f"(b));
    return d;
}
__device__ __forceinline__ float2 unpack2(ull v) {
    float2 r;
    asm("mov.b64 {%0, %1}, %2;" : "=f"(r.x), "=f"(r.y) : "l"(v));
    return r;
}
__device__ __forceinline__ u32 smem_u32(const void* p) {
    u32 a;
    asm("{ .reg .u64 t; cvta.to.shared.u64 t, %1; cvt.u32.u64 %0, t; }"
        : "=r"(a) : "l"(p));
    return a;
}
// cp.async 16B with dynamic src-size (0 => zero-fill)
__device__ __forceinline__ void cp16(u32 dst, const void* src, u32 bytes) {
    asm volatile("cp.async.cg.shared.global [%0], [%1], 16, %2;"
                 :: "r"(dst), "l"(src), "r"(bytes));
}
#define CP_COMMIT() asm volatile("cp.async.commit_group;" ::: "memory")

// ---------------- scratch buffers ----------------
__device__ float g_y3d [NPTS * 16];
__device__ float g_c2d [NPTS * 64];
__device__ float g_mix [NPTS * 80];
__device__ float g_h   [NPTS * 80];
__device__ float g_a   [NPTS * 80];

__device__ __align__(16) __nv_bfloat16 g_p2h [NPTS * 64];
__device__ __align__(16) __nv_bfloat16 g_p2l [NPTS * 64];
__device__ __align__(16) __nv_bfloat16 g_mixh[NPTS * 80];
__device__ __align__(16) __nv_bfloat16 g_mixl[NPTS * 80];
__device__ __align__(16) __nv_bfloat16 g_th  [NPTS * 80];
__device__ __align__(16) __nv_bfloat16 g_tl  [NPTS * 80];
__device__ __align__(16) __nv_bfloat16 g_hh  [NPTS * 80];
__device__ __align__(16) __nv_bfloat16 g_hl  [NPTS * 80];

// transposed/split weights [27][COUT][CIN] bf16
__device__ __align__(16) __nv_bfloat16 g_w2h [KOFF * 64 * 64];
__device__ __align__(16) __nv_bfloat16 g_w2l [KOFF * 64 * 64];
__device__ __align__(16) __nv_bfloat16 g_wm1h[KOFF * 80 * 80];
__device__ __align__(16) __nv_bfloat16 g_wm1l[KOFF * 80 * 80];
__device__ __align__(16) __nv_bfloat16 g_wm2h[KOFF * 80 * 80];
__device__ __align__(16) __nv_bfloat16 g_wm2l[KOFF * 80 * 80];
__device__ __align__(16) __nv_bfloat16 g_wa1h[KOFF * 80 * 80];
__device__ __align__(16) __nv_bfloat16 g_wa1l[KOFF * 80 * 80];
__device__ __align__(16) __nv_bfloat16 g_wa2h[KOFF * 80 * 80];
__device__ __align__(16) __nv_bfloat16 g_wa2l[KOFF * 80 * 80];

__device__ __forceinline__ void split_bf16(float v, __nv_bfloat16& h, __nv_bfloat16& l) {
    h = __float2bfloat16(v);
    l = __float2bfloat16(v - __bfloat162float(h));
}

// =====================================================================
// prep: W [27][CIN][COUT] fp32 -> Wt hi/lo [27][COUT][CIN] bf16
// =====================================================================
__global__ void prep_w(const float* __restrict__ W,
                       __nv_bfloat16* __restrict__ Wh,
                       __nv_bfloat16* __restrict__ Wl, int CIN, int COUT)
{
    int tot = KOFF * CIN * COUT;
    for (int i = blockIdx.x * blockDim.x + threadIdx.x; i < tot;
         i += gridDim.x * blockDim.x) {
        int k = i / (CIN * COUT);
        int rem = i - k * (CIN * COUT);
        int c = rem / COUT, n = rem - c * COUT;
        float v = W[i];
        __nv_bfloat16 h, l;
        split_bf16(v, h, l);
        int o = (k * COUT + n) * CIN + c;
        Wh[o] = h; Wl[o] = l;
    }
}

// =====================================================================
// conv16 (SIMT) -> y3d fp32, mix[:,0:16] fp32 + bf16 hi/lo
// =====================================================================
__global__ void __launch_bounds__(256)
conv16_kernel(const float* __restrict__ x, const int* __restrict__ nbr,
              const float* __restrict__ W, const float* __restrict__ gamma,
              const float* __restrict__ beta,
              float* __restrict__ y3d, float* __restrict__ mix,
              __nv_bfloat16* __restrict__ mixh, __nv_bfloat16* __restrict__ mixl,
              int n)
{
    __shared__ float Wsh[KOFF * 16 * 16];
    for (int t = threadIdx.x; t < KOFF * 64; t += 256)
        ((float4*)Wsh)[t] = ((const float4*)W)[t];
    __syncthreads();

    int row = blockIdx.x * 256 + threadIdx.x;
    if (row >= n) return;

    ull acc[8];
#pragma unroll
    for (int p = 0; p < 8; p++) acc[p] = 0ull;

    const int* nb = nbr + (size_t)row * KOFF;
    for (int k = 0; k < KOFF; k++) {
        int idx = __ldg(nb + k);
        if (idx < 0) continue;
        const float* f = x + (size_t)idx * 16;
#pragma unroll
        for (int cq = 0; cq < 4; cq++) {
            float4 a = *(const float4*)(f + 4 * cq);
#pragma unroll
            for (int cc = 0; cc < 4; cc++) {
                float fv = (cc == 0) ? a.x : (cc == 1) ? a.y : (cc == 2) ? a.z : a.w;
                ull p2 = pack2(fv);
                const ulonglong2* br =
                    (const ulonglong2*)(Wsh + (k * 16 + cq * 4 + cc) * 16);
#pragma unroll
                for (int q = 0; q < 4; q++) {
                    ulonglong2 b = br[q];
                    acc[2*q]   = ffma2(p2, b.x, acc[2*q]);
                    acc[2*q+1] = ffma2(p2, b.y, acc[2*q+1]);
                }
            }
        }
    }
    float* yo = y3d + (size_t)row * 16;
    float* mo = mix + (size_t)row * 80;
    __nv_bfloat16* mh = mixh + (size_t)row * 80;
    __nv_bfloat16* ml = mixl + (size_t)row * 80;
#pragma unroll
    for (int p = 0; p < 8; p++) {
        float2 v = unpack2(acc[p]);
        int j = 2 * p;
        float v0 = fmaxf(v.x * __ldg(gamma + j)     + __ldg(beta + j),     0.f);
        float v1 = fmaxf(v.y * __ldg(gamma + j + 1) + __ldg(beta + j + 1), 0.f);
        float2 o = make_float2(v0, v1);
        *(float2*)(yo + j) = o;
        *(float2*)(mo + j) = o;
        __nv_bfloat16 h0, l0, h1, l1;
        split_bf16(v0, h0, l0);
        split_bf16(v1, h1, l1);
        mh[j] = h0; mh[j+1] = h1;
        ml[j] = l0; ml[j+1] = l1;
    }
}

// =====================================================================
// FUSED dual-gate kernel: computes BOTH
//   p2d = (relu(y3d@Wg+bg) * f2g) @ Wp   (bf16 hi/lo out)
//   c2d = (relu(y3d@Wc+bc) * f2g) @ Wp   (fp32 out)
// sharing the f2g load and the Wp SMEM row between both projections.
// 256 thr: thread = (row r = tid>>1, col-half = tid&1, 32 cols each).
// =====================================================================
#define G2_WSG  0
#define G2_WSC  4144
#define G2_BG   8288
#define G2_BC   8548
#define G2_WP   8808
#define GATE2_FLOATS (G2_WP + 16576)   // 25384 floats = 101536 B

__global__ void __launch_bounds__(256)
gate2_kernel(const float* __restrict__ y3d, const float* __restrict__ f2d,
             const int* __restrict__ nn_idx,
             const float* __restrict__ Wg, const float* __restrict__ bg,
             const float* __restrict__ Wc, const float* __restrict__ bc,
             const float* __restrict__ Wp,
             __nv_bfloat16* __restrict__ p2h, __nv_bfloat16* __restrict__ p2l,
             float* __restrict__ c2d, int n)
{
    extern __shared__ float sh[];
    float* WsG = sh + G2_WSG;   // [259][16]
    float* WsC = sh + G2_WSC;   // [259][16]
    float* bG  = sh + G2_BG;    // [259]
    float* bC  = sh + G2_BC;    // [259]
    float* Wps = sh + G2_WP;    // [259][64]

    for (int t = threadIdx.x; t < 259 * 16; t += 256) {
        int c = t / 259, j = t - c * 259;
        WsG[j * 16 + c] = Wg[t];
        WsC[j * 16 + c] = Wc[t];
    }
    for (int t = threadIdx.x; t < 259; t += 256) { bG[t] = bg[t]; bC[t] = bc[t]; }
    for (int t = threadIdx.x; t < 259 * 16; t += 256)
        ((float4*)Wps)[t] = ((const float4*)Wp)[t];
    __syncthreads();

    const int r    = threadIdx.x >> 1;
    const int half = threadIdx.x & 1;
    const int row  = blockIdx.x * 128 + r;
    if (row >= n) return;
    const int jb = half * 32;

    ull accp[16], accc[16];
#pragma unroll
    for (int p = 0; p < 16; p++) { accp[p] = 0ull; accc[p] = 0ull; }

    int fi = nn_idx[row];
    if (fi >= 0) {
        ull y2[8];
#pragma unroll
        for (int cq = 0; cq < 4; cq++) {
            float4 v = *(const float4*)(y3d + (size_t)row * 16 + 4 * cq);
            y2[2*cq]   = packf2(v.x, v.y);
            y2[2*cq+1] = packf2(v.z, v.w);
        }
        const float* fr = f2d + (size_t)fi * 259;
#pragma unroll 2
        for (int j = 0; j < 259; j++) {
            const ulonglong2* wg = (const ulonglong2*)(WsG + j * 16);
            const ulonglong2* wc = (const ulonglong2*)(WsC + j * 16);
            ull dg = 0ull, dc = 0ull;
#pragma unroll
            for (int q = 0; q < 4; q++) {
                ulonglong2 a = wg[q];
                dg = ffma2(y2[2*q],   a.x, dg);
                dg = ffma2(y2[2*q+1], a.y, dg);
                ulonglong2 b = wc[q];
                dc = ffma2(y2[2*q],   b.x, dc);
                dc = ffma2(y2[2*q+1], b.y, dc);
            }
            float f = __ldg(fr + j);
            float2 g2 = unpack2(dg);
            float2 c2 = unpack2(dc);
            float sg = fmaxf(g2.x + g2.y + bG[j], 0.f) * f;
            float sc = fmaxf(c2.x + c2.y + bC[j], 0.f) * f;
            ull sg2 = pack2(sg), sc2 = pack2(sc);
            const ulonglong2* wp = (const ulonglong2*)(Wps + j * 64 + jb);
#pragma unroll
            for (int q = 0; q < 8; q++) {
                ulonglong2 w = wp[q];
                accp[2*q]   = ffma2(sg2, w.x, accp[2*q]);
                accp[2*q+1] = ffma2(sg2, w.y, accp[2*q+1]);
                accc[2*q]   = ffma2(sc2, w.x, accc[2*q]);
                accc[2*q+1] = ffma2(sc2, w.y, accc[2*q+1]);
            }
        }
    }
    // outputs
    __nv_bfloat16* oh = p2h + (size_t)row * 64 + jb;
    __nv_bfloat16* ol = p2l + (size_t)row * 64 + jb;
#pragma unroll
    for (int i = 0; i < 16; i++) {
        float2 v = unpack2(accp[i]);
        __nv_bfloat16 h0, l0, h1, l1;
        split_bf16(v.x, h0, l0);
        split_bf16(v.y, h1, l1);
        *(__nv_bfloat162*)(oh + 2*i) = __nv_bfloat162(h0, h1);
        *(__nv_bfloat162*)(ol + 2*i) = __nv_bfloat162(l0, l1);
    }
    float* oc = c2d + (size_t)row * 64 + jb;
#pragma unroll
    for (int q = 0; q < 8; q++) {
        float2 a = unpack2(accc[2*q]);
        float2 b = unpack2(accc[2*q+1]);
        *(float4*)(oc + 4*q) = make_float4(a.x, a.y, b.x, b.y);
    }
}

// =====================================================================
// WMMA conv v2: bf16x3, cp.async double-buffered feature gather.
// 256 thr / 8 warps / 256 rows. Per k: cp.async stage F(k+1) overlaps
// compute(k); weights for k+1 prefetched to regs during compute, STS'd
// after. EPI 0: relu(v*g+b)  1: relu(v*g+b)+res  2: relu(v*g+b+res)
// =====================================================================
template <int CIN, int COUT, int EPI>
__global__ void __launch_bounds__(256)
wmmaconv_kernel(const __nv_bfloat16* __restrict__ fh,
                const __nv_bfloat16* __restrict__ fl,
                const int* __restrict__ nbr,
                const __nv_bfloat16* __restrict__ wh,
                const __nv_bfloat16* __restrict__ wl,
                const float* __restrict__ gamma, const float* __restrict__ beta,
                const float* __restrict__ res, int resStride, int resCol0,
                float* __restrict__ outF, int ofStride, int ofCol0,
                __nv_bfloat16* __restrict__ outH, __nv_bfloat16* __restrict__ outL,
                int obStride, int obCol0, int n)
{
    constexpr int ROWS = 256;
    constexpr int KT   = CIN / 16;
    constexpr int NT   = COUT / 16;
    constexpr int SP   = CIN + 8;             // conflict-free ldmatrix stride
    constexpr int NCH  = CIN / 8;             // 16B chunks per row
    constexpr int CP   = COUT + 4;            // fp32 epilogue stride
    constexpr int FBUF = 2 * ROWS * SP * 2;   // hi+lo, one stage buffer (bytes)
    constexpr int LOFF = ROWS * SP * 2;       // lo offset inside a buffer
    constexpr int WB   = COUT * SP * 2;       // one weight plane (bytes)
    constexpr int WPRE = (COUT * NCH + 255) / 256;

    extern __shared__ char smc[];
    const u32 sbase = smem_u32(smc);
    const u32 wbase = sbase + 2 * FBUF;

    const int tid  = threadIdx.x;
    const int warp = tid >> 5;
    const int rowbase = blockIdx.x * ROWS;
    const int m0 = warp * 32;

    // ---- cp.async staging of gathered features ----
    auto cpF = [&](int k, int buf) {
        u32 fb = sbase + buf * FBUF;
#pragma unroll 2
        for (int e = tid; e < ROWS * NCH; e += 256) {
            int r = e / NCH, c = e - r * NCH;
            int row = rowbase + r;
            int idx = (row < n) ? __ldg(nbr + (size_t)row * KOFF + k) : -1;
            const char* sh = (const char*)fh;
            const char* sl = (const char*)fl;
            u32 bytes = 0;
            if (idx >= 0) {
                size_t bo = (size_t)idx * CIN * 2 + (size_t)c * 16;
                sh += bo; sl += bo; bytes = 16;
            }
            u32 d = fb + (u32)(r * SP + c * 8) * 2;
            cp16(d, sh, bytes);
            cp16(d + LOFF, sl, bytes);
        }
    };

    // prologue: stage F(0) + W(0)
    cpF(0, 0);
    {
        const char* whk = (const char*)(wh + (size_t)0 * COUT * CIN);
        const char* wlk = (const char*)(wl + (size_t)0 * COUT * CIN);
        for (int e = tid; e < COUT * NCH; e += 256) {
            int r = e / NCH, c = e - r * NCH;
            size_t bo = (size_t)r * CIN * 2 + (size_t)c * 16;
            u32 d = wbase + (u32)(r * SP + c * 8) * 2;
            cp16(d, whk + bo, 16);
            cp16(d + WB, wlk + bo, 16);
        }
    }
    CP_COMMIT();

    wmma::fragment<wmma::accumulator, 16, 16, 16, float> acc[2][NT];
#pragma unroll
    for (int m = 0; m < 2; m++)
#pragma unroll
        for (int nn = 0; nn < NT; nn++) wmma::fill_fragment(acc[m][nn], 0.f);

    for (int k = 0; k < KOFF; k++) {
        const int buf = k & 1;
        const bool pre = (k + 1 < KOFF);
        if (pre) { cpF(k + 1, buf ^ 1); CP_COMMIT(); }

        // prefetch next weights into registers (completes during compute)
        uint4 wph[WPRE], wpl[WPRE];
        if (pre) {
            const char* whk = (const char*)(wh + (size_t)(k + 1) * COUT * CIN);
            const char* wlk = (const char*)(wl + (size_t)(k + 1) * COUT * CIN);
            int i = 0;
#pragma unroll
            for (int e = tid; e < COUT * NCH; e += 256, i++) {
                size_t bo = (size_t)(e / NCH) * CIN * 2 + (size_t)(e % NCH) * 16;
                wph[i] = *(const uint4*)(whk + bo);
                wpl[i] = *(const uint4*)(wlk + bo);
            }
        }

        if (pre) asm volatile("cp.async.wait_group 1;" ::: "memory");
        else     asm volatile("cp.async.wait_group 0;" ::: "memory");
        __syncthreads();

        // ---- compute ----
        const __nv_bfloat16* Fh = (const __nv_bfloat16*)(smc + buf * FBUF);
        const __nv_bfloat16* Fl = Fh + ROWS * SP;
        const __nv_bfloat16* Ws = (const __nv_bfloat16*)(smc + 2 * FBUF);
        const __nv_bfloat16* Wl = Ws + COUT * SP;
#pragma unroll
        for (int kk = 0; kk < KT; kk++) {
            wmma::fragment<wmma::matrix_a, 16, 16, 16, __nv_bfloat16,
                           wmma::row_major> Ah[2], Al[2];
#pragma unroll
            for (int m = 0; m < 2; m++) {
                wmma::load_matrix_sync(Ah[m], Fh + (m0 + m * 16) * SP + kk * 16, SP);
                wmma::load_matrix_sync(Al[m], Fl + (m0 + m * 16) * SP + kk * 16, SP);
            }
#pragma unroll
            for (int nn = 0; nn < NT; nn++) {
                wmma::fragment<wmma::matrix_b, 16, 16, 16, __nv_bfloat16,
                               wmma::col_major> Bh, Bl;
                wmma::load_matrix_sync(Bh, Ws + (nn * 16) * SP + kk * 16, SP);
                wmma::load_matrix_sync(Bl, Wl + (nn * 16) * SP + kk * 16, SP);
#pragma unroll
                for (int m = 0; m < 2; m++) {
                    wmma::mma_sync(acc[m][nn], Ah[m], Bh, acc[m][nn]);
                    wmma::mma_sync(acc[m][nn], Ah[m], Bl, acc[m][nn]);
                    wmma::mma_sync(acc[m][nn], Al[m], Bh, acc[m][nn]);
                }
            }
        }
        __syncthreads();

        // store prefetched weights for k+1
        if (pre) {
            int i = 0;
#pragma unroll
            for (int e = tid; e < COUT * NCH; e += 256, i++) {
                int r = e / NCH, c = e - r * NCH;
                char* d = smc + 2 * FBUF + (r * SP + c * 8) * 2;
                *(uint4*)d = wph[i];
                *(uint4*)(d + WB) = wpl[i];
            }
        }
        // next iteration's __syncthreads (after wait) orders these STS
    }
    __syncthreads();

    // ---- epilogue: frags -> SMEM fp32, then fused bn/relu/residual ----
    float* C = (float*)smc;   // [ROWS][CP]
#pragma unroll
    for (int m = 0; m < 2; m++)
#pragma unroll
        for (int nn = 0; nn < NT; nn++)
            wmma::store_matrix_sync(C + (m0 + m * 16) * CP + nn * 16,
                                    acc[m][nn], CP, wmma::mem_row_major);
    __syncthreads();

    for (int e = tid; e < ROWS * COUT; e += 256) {
        int r = e / COUT, j = e - r * COUT;
        int row = rowbase + r;
        if (row >= n) break;
        float v = C[r * CP + j] * __ldg(gamma + j) + __ldg(beta + j);
        float rv = 0.f;
        if (EPI != 0) rv = res[(size_t)row * resStride + resCol0 + j];
        if (EPI == 2) v += rv;
        v = fmaxf(v, 0.f);
        if (EPI == 1) v += rv;
        if (outF) outF[(size_t)row * ofStride + ofCol0 + j] = v;
        if (outH) {
            __nv_bfloat16 h, l;
            split_bf16(v, h, l);
            outH[(size_t)row * obStride + obCol0 + j] = h;
            outL[(size_t)row * obStride + obCol0 + j] = l;
        }
    }
}

// =====================================================================
// SIMT conv (downsample layer only): CIN=80 -> COUT=96
// =====================================================================
template <int CIN, int COUT, int EPI>
__global__ void __launch_bounds__(256)
conv3_kernel(const float* __restrict__ feats, const int* __restrict__ nbr,
             const float* __restrict__ W, const float* __restrict__ gamma,
             const float* __restrict__ beta, const float* __restrict__ res,
             float* __restrict__ out, int n_out, int out_stride, int out_col0)
{
    constexpr int TN   = COUT / 4;
    constexpr int NV   = CIN / 4;
    constexpr int CPAD = (CIN == 64) ? 68 : 84;
    constexpr int WSZ  = CIN * COUT;

    extern __shared__ float smf[];
    float* F  = smf;
    float* Wb = smf + 128 * CPAD;

    const int tid  = threadIdx.x;
    const int warp = tid >> 5, lane = tid & 31;
    const int ng = lane >> 3, rg = lane & 7;
    const int jb = ng * TN;
    const int rowbase = blockIdx.x * 128;
    const int rl0 = warp * 16 + rg;

    ull acc[2][TN / 2];
#pragma unroll
    for (int r = 0; r < 2; r++)
#pragma unroll
        for (int p = 0; p < TN / 2; p++) acc[r][p] = 0ull;

    for (int k = 0; k < KOFF; k++) {
        __syncthreads();
        {
            const float4* src = (const float4*)(W + (size_t)k * WSZ);
            float4* dst = (float4*)Wb;
            for (int t = tid; t < WSZ / 4; t += 256) dst[t] = src[t];
        }
        for (int e = tid; e < 128 * NV; e += 256) {
            int r  = e / NV;
            int c4 = e - r * NV;
            int grow = rowbase + r;
            float4 v = make_float4(0.f, 0.f, 0.f, 0.f);
            if (grow < n_out) {
                int idx = __ldg(nbr + (size_t)grow * KOFF + k);
                if (idx >= 0)
                    v = *(const float4*)(feats + (size_t)idx * CIN + 4 * c4);
            }
            *(float4*)(F + r * CPAD + 4 * c4) = v;
        }
        __syncthreads();

        const float* F0 = F + rl0 * CPAD;
        const float* F1 = F0 + 8 * CPAD;
#pragma unroll
        for (int cq = 0; cq < NV; cq++) {
            float4 a0 = *(const float4*)(F0 + 4 * cq);
            float4 a1 = *(const float4*)(F1 + 4 * cq);
#pragma unroll
            for (int cc = 0; cc < 4; cc++) {
                float v0 = (cc == 0) ? a0.x : (cc == 1) ? a0.y : (cc == 2) ? a0.z : a0.w;
                float v1 = (cc == 0) ? a1.x : (cc == 1) ? a1.y : (cc == 2) ? a1.z : a1.w;
                ull p0 = pack2(v0), p1 = pack2(v1);
                const ulonglong2* br =
                    (const ulonglong2*)(Wb + (cq * 4 + cc) * COUT + jb);
#pragma unroll
                for (int q = 0; q < TN / 4; q++) {
                    ulonglong2 b = br[q];
                    acc[0][2*q]   = ffma2(p0, b.x, acc[0][2*q]);
                    acc[0][2*q+1] = ffma2(p0, b.y, acc[0][2*q+1]);
                    acc[1][2*q]   = ffma2(p1, b.x, acc[1][2*q]);
                    acc[1][2*q+1] = ffma2(p1, b.y, acc[1][2*q+1]);
                }
            }
        }
    }

#pragma unroll
    for (int r = 0; r < 2; r++) {
        int row = rowbase + rl0 + 8 * r;
        if (row >= n_out) continue;
        float* o = out + (size_t)row * out_stride + out_col0 + jb;
        const float* rr = (EPI != 0) ? (res + (size_t)row * COUT + jb) : nullptr;
#pragma unroll
        for (int p = 0; p < TN / 2; p++) {
            float2 v = unpack2(acc[r][p]);
            int j = jb + 2 * p;
            float x0 = v.x * __ldg(gamma + j)     + __ldg(beta + j);
            float x1 = v.y * __ldg(gamma + j + 1) + __ldg(beta + j + 1);
            float r0v = 0.f, r1v = 0.f;
            if (EPI != 0) { r0v = rr[2*p]; r1v = rr[2*p + 1]; }
            if (EPI == 2) { x0 += r0v; x1 += r1v; }
            x0 = fmaxf(x0, 0.f);
            x1 = fmaxf(x1, 0.f);
            if (EPI == 1) { x0 += r0v; x1 += r1v; }
            *(float2*)(o + 2 * p) = make_float2(x0, x1);
        }
    }
}

#define SMEM_C96   ((128 * 84 + 80 * 96) * 4)
// v2 wmma smem: 2 F stage buffers (hi+lo) + 1 weight buffer (hi+lo)
#define SMEM_W64   (2 * (2 * 256 * 72 * 2) + (2 * 64 * 72 * 2))   // 165888
#define SMEM_W80   (2 * (2 * 256 * 88 * 2) + (2 * 80 * 88 * 2))   // 208384

// =====================================================================
// Launch
// =====================================================================
extern "C" void kernel_launch(void* const* d_in, const int* in_sizes, int n_in,
                              void* d_out, int out_size)
{
    const float* x3d    = (const float*)d_in[0];
    const float* f2d    = (const float*)d_in[1];
    const int*   nn_idx = (const int*)  d_in[2];
    const int*   nbr    = (const int*)  d_in[3];
    const int*   nbr_ds = (const int*)  d_in[4];
    const float* W3d    = (const float*)d_in[5];
    const float* g3d    = (const float*)d_in[6];
    const float* b3d    = (const float*)d_in[7];
    const float* Wg     = (const float*)d_in[8];
    const float* bg     = (const float*)d_in[9];
    const float* Wc     = (const float*)d_in[10];
    const float* bc     = (const float*)d_in[11];
    const float* Wp     = (const float*)d_in[12];
    const float* W2d    = (const float*)d_in[13];
    const float* g2d    = (const float*)d_in[14];
    const float* b2d    = (const float*)d_in[15];
    const float* Wm1    = (const float*)d_in[16];
    const float* gm1    = (const float*)d_in[17];
    const float* bm1    = (const float*)d_in[18];
    const float* Wm2    = (const float*)d_in[19];
    const float* gm2    = (const float*)d_in[20];
    const float* bm2    = (const float*)d_in[21];
    const float* Wa1    = (const float*)d_in[22];
    const float* ga1    = (const float*)d_in[23];
    const float* ba1    = (const float*)d_in[24];
    const float* Wa2    = (const float*)d_in[25];
    const float* ga2    = (const float*)d_in[26];
    const float* ba2    = (const float*)d_in[27];
    const float* Wds    = (const float*)d_in[28];
    const float* gds    = (const float*)d_in[29];
    const float* bds    = (const float*)d_in[30];
    float* out = (float*)d_out;

    float *y3d, *c2d, *mix, *hbuf, *abuf;
    cudaGetSymbolAddress((void**)&y3d,  g_y3d);
    cudaGetSymbolAddress((void**)&c2d,  g_c2d);
    cudaGetSymbolAddress((void**)&mix,  g_mix);
    cudaGetSymbolAddress((void**)&hbuf, g_h);
    cudaGetSymbolAddress((void**)&abuf, g_a);

    __nv_bfloat16 *p2h, *p2l, *mixh, *mixl, *th, *tl, *hh, *hl;
    cudaGetSymbolAddress((void**)&p2h,  g_p2h);
    cudaGetSymbolAddress((void**)&p2l,  g_p2l);
    cudaGetSymbolAddress((void**)&mixh, g_mixh);
    cudaGetSymbolAddress((void**)&mixl, g_mixl);
    cudaGetSymbolAddress((void**)&th,   g_th);
    cudaGetSymbolAddress((void**)&tl,   g_tl);
    cudaGetSymbolAddress((void**)&hh,   g_hh);
    cudaGetSymbolAddress((void**)&hl,   g_hl);

    __nv_bfloat16 *w2h, *w2l, *wm1h, *wm1l, *wm2h, *wm2l, *wa1h, *wa1l, *wa2h, *wa2l;
    cudaGetSymbolAddress((void**)&w2h,  g_w2h);
    cudaGetSymbolAddress((void**)&w2l,  g_w2l);
    cudaGetSymbolAddress((void**)&wm1h, g_wm1h);
    cudaGetSymbolAddress((void**)&wm1l, g_wm1l);
    cudaGetSymbolAddress((void**)&wm2h, g_wm2h);
    cudaGetSymbolAddress((void**)&wm2l, g_wm2l);
    cudaGetSymbolAddress((void**)&wa1h, g_wa1h);
    cudaGetSymbolAddress((void**)&wa1l, g_wa1l);
    cudaGetSymbolAddress((void**)&wa2h, g_wa2h);
    cudaGetSymbolAddress((void**)&wa2l, g_wa2l);

    cudaFuncSetAttribute(gate2_kernel, cudaFuncAttributeMaxDynamicSharedMemorySize,
                         GATE2_FLOATS * (int)sizeof(float));
    cudaFuncSetAttribute(wmmaconv_kernel<64, 64, 1>,
                         cudaFuncAttributeMaxDynamicSharedMemorySize, SMEM_W64);
    cudaFuncSetAttribute(wmmaconv_kernel<80, 80, 0>,
                         cudaFuncAttributeMaxDynamicSharedMemorySize, SMEM_W80);
    cudaFuncSetAttribute(wmmaconv_kernel<80, 80, 2>,
                         cudaFuncAttributeMaxDynamicSharedMemorySize, SMEM_W80);
    cudaFuncSetAttribute(conv3_kernel<80, 96, 0>,
                         cudaFuncAttributeMaxDynamicSharedMemorySize, SMEM_C96);

    const int B256 = (NPTS + 255) / 256;
    const int BC   = (NPTS + 255) / 256;   // 313 blocks of 256 rows
    const int BG   = (NPTS + 127) / 128;   // 625 (gate2: 128 rows/block)
    const int BDS  = (NDPTS + 127) / 128;  // 79

    // 0. weight transpose + bf16 split
    prep_w<<<(KOFF*64*64 + 255)/256, 256>>>(W2d, w2h, w2l, 64, 64);
    prep_w<<<(KOFF*80*80 + 255)/256, 256>>>(Wm1, wm1h, wm1l, 80, 80);
    prep_w<<<(KOFF*80*80 + 255)/256, 256>>>(Wm2, wm2h, wm2l, 80, 80);
    prep_w<<<(KOFF*80*80 + 255)/256, 256>>>(Wa1, wa1h, wa1l, 80, 80);
    prep_w<<<(KOFF*80*80 + 255)/256, 256>>>(Wa2, wa2h, wa2l, 80, 80);

    // 1. y3d + mix[:,0:16]
    conv16_kernel<<<B256, 256>>>(x3d, nbr, W3d, g3d, b3d, y3d, mix, mixh, mixl, NPTS);

    // 2. fused dual gate: p2d (bf16 hi/lo) + c2d (fp32) in one pass
    gate2_kernel<<<BG, 256, GATE2_FLOATS * sizeof(float)>>>(
        y3d, f2d, nn_idx, Wg, bg, Wc, bc, Wp, p2h, p2l, c2d, NPTS);

    // 3. mix[:,16:80] = bn_relu(conv64(p2d)) + c2d
    wmmaconv_kernel<64, 64, 1><<<BC, 256, SMEM_W64>>>(
        p2h, p2l, nbr, w2h, w2l, g2d, b2d,
        c2d, 64, 0, mix, 80, 16, mixh, mixl, 80, 16, NPTS);

    // 4. t = bn_relu(conv80(mix, Wm1))  (bf16 only)
    wmmaconv_kernel<80, 80, 0><<<BC, 256, SMEM_W80>>>(
        mixh, mixl, nbr, wm1h, wm1l, gm1, bm1,
        nullptr, 0, 0, nullptr, 0, 0, th, tl, 80, 0, NPTS);

    // 5. h = relu(conv80(t, Wm2)*g + b + mix)  (fp32 + bf16)
    wmmaconv_kernel<80, 80, 2><<<BC, 256, SMEM_W80>>>(
        th, tl, nbr, wm2h, wm2l, gm2, bm2,
        mix, 80, 0, hbuf, 80, 0, hh, hl, 80, 0, NPTS);

    // 6. t = bn_relu(conv80(h, Wa1))  (bf16 only)
    wmmaconv_kernel<80, 80, 0><<<BC, 256, SMEM_W80>>>(
        hh, hl, nbr, wa1h, wa1l, ga1, ba1,
        nullptr, 0, 0, nullptr, 0, 0, th, tl, 80, 0, NPTS);

    // 7. a = relu(conv80(t, Wa2)*g + b + h)  (fp32 only)
    wmmaconv_kernel<80, 80, 2><<<BC, 256, SMEM_W80>>>(
        th, tl, nbr, wa2h, wa2l, ga2, ba2,
        hbuf, 80, 0, abuf, 80, 0, nullptr, nullptr, 80, 0, NPTS);

    // 8. out = bn_relu(conv80->96(a, nbr_ds, Wds))  (SIMT)
    conv3_kernel<80, 96, 0><<<BDS, 256, SMEM_C96>>>(
        abuf, nbr_ds, Wds, gds, bds, nullptr, out, NDPTS, 96, 0);
}

// round 14
// speedup vs baseline: 1.2590x; 1.2590x over previous
#include <cuda_runtime.h>
#include <cuda_bf16.h>
#include <mma.h>
#include <cstdint>

#define NPTS   80000
#define NDPTS  10000
#define KOFF   27

typedef unsigned long long ull;
typedef unsigned int u32;

using namespace nvcuda;

// ---------------- packed fp32x2 helpers ----------------
__device__ __forceinline__ ull ffma2(ull a, ull b, ull c) {
    ull d;
    asm("fma.rn.f32x2 %0, %1, %2, %3;" : "=l"(d) : "l"(a), "l"(b), "l"(c));
    return d;
}
__device__ __forceinline__ ull pack2(float v) {
    ull d;
    asm("mov.b64 %0, {%1, %1};" : "=l"(d) : "f"(v));
    return d;
}
__device__ __forceinline__ ull packf2(float a, float b) {
    ull d;
    asm("mov.b64 %0, {%1, %2};" : "=l"(d) : "f"(a), "f"(b));
    return d;
}
__device__ __forceinline__ float2 unpack2(ull v) {
    float2 r;
    asm("mov.b64 {%0, %1}, %2;" : "=f"(r.x), "=f"(r.y) : "l"(v));
    return r;
}

// ---------------- scratch buffers ----------------
__device__ float g_y3d [NPTS * 16];
__device__ float g_c2d [NPTS * 64];
__device__ float g_mix [NPTS * 80];
__device__ float g_h   [NPTS * 80];
__device__ float g_a   [NPTS * 80];

__device__ __align__(16) __nv_bfloat16 g_p2h [NPTS * 64];
__device__ __align__(16) __nv_bfloat16 g_p2l [NPTS * 64];
__device__ __align__(16) __nv_bfloat16 g_mixh[NPTS * 80];
__device__ __align__(16) __nv_bfloat16 g_mixl[NPTS * 80];
__device__ __align__(16) __nv_bfloat16 g_th  [NPTS * 80];
__device__ __align__(16) __nv_bfloat16 g_tl  [NPTS * 80];
__device__ __align__(16) __nv_bfloat16 g_hh  [NPTS * 80];
__device__ __align__(16) __nv_bfloat16 g_hl  [NPTS * 80];

// transposed/split weights [27][COUT][CIN] bf16
__device__ __align__(16) __nv_bfloat16 g_w2h [KOFF * 64 * 64];
__device__ __align__(16) __nv_bfloat16 g_w2l [KOFF * 64 * 64];
__device__ __align__(16) __nv_bfloat16 g_wm1h[KOFF * 80 * 80];
__device__ __align__(16) __nv_bfloat16 g_wm1l[KOFF * 80 * 80];
__device__ __align__(16) __nv_bfloat16 g_wm2h[KOFF * 80 * 80];
__device__ __align__(16) __nv_bfloat16 g_wm2l[KOFF * 80 * 80];
__device__ __align__(16) __nv_bfloat16 g_wa1h[KOFF * 80 * 80];
__device__ __align__(16) __nv_bfloat16 g_wa1l[KOFF * 80 * 80];
__device__ __align__(16) __nv_bfloat16 g_wa2h[KOFF * 80 * 80];
__device__ __align__(16) __nv_bfloat16 g_wa2l[KOFF * 80 * 80];

__device__ __forceinline__ void split_bf16(float v, __nv_bfloat16& h, __nv_bfloat16& l) {
    h = __float2bfloat16(v);
    l = __float2bfloat16(v - __bfloat162float(h));
}

// =====================================================================
// prep: W [27][CIN][COUT] fp32 -> Wt hi/lo [27][COUT][CIN] bf16
// =====================================================================
__global__ void prep_w(const float* __restrict__ W,
                       __nv_bfloat16* __restrict__ Wh,
                       __nv_bfloat16* __restrict__ Wl, int CIN, int COUT)
{
    int tot = KOFF * CIN * COUT;
    for (int i = blockIdx.x * blockDim.x + threadIdx.x; i < tot;
         i += gridDim.x * blockDim.x) {
        int k = i / (CIN * COUT);
        int rem = i - k * (CIN * COUT);
        int c = rem / COUT, n = rem - c * COUT;
        float v = W[i];
        __nv_bfloat16 h, l;
        split_bf16(v, h, l);
        int o = (k * COUT + n) * CIN + c;
        Wh[o] = h; Wl[o] = l;
    }
}

// =====================================================================
// conv16 (SIMT) -> y3d fp32, mix[:,0:16] fp32 + bf16 hi/lo
// =====================================================================
__global__ void __launch_bounds__(256)
conv16_kernel(const float* __restrict__ x, const int* __restrict__ nbr,
              const float* __restrict__ W, const float* __restrict__ gamma,
              const float* __restrict__ beta,
              float* __restrict__ y3d, float* __restrict__ mix,
              __nv_bfloat16* __restrict__ mixh, __nv_bfloat16* __restrict__ mixl,
              int n)
{
    __shared__ float Wsh[KOFF * 16 * 16];
    for (int t = threadIdx.x; t < KOFF * 64; t += 256)
        ((float4*)Wsh)[t] = ((const float4*)W)[t];
    __syncthreads();

    int row = blockIdx.x * 256 + threadIdx.x;
    if (row >= n) return;

    ull acc[8];
#pragma unroll
    for (int p = 0; p < 8; p++) acc[p] = 0ull;

    const int* nb = nbr + (size_t)row * KOFF;
    for (int k = 0; k < KOFF; k++) {
        int idx = __ldg(nb + k);
        if (idx < 0) continue;
        const float* f = x + (size_t)idx * 16;
#pragma unroll
        for (int cq = 0; cq < 4; cq++) {
            float4 a = *(const float4*)(f + 4 * cq);
#pragma unroll
            for (int cc = 0; cc < 4; cc++) {
                float fv = (cc == 0) ? a.x : (cc == 1) ? a.y : (cc == 2) ? a.z : a.w;
                ull p2 = pack2(fv);
                const ulonglong2* br =
                    (const ulonglong2*)(Wsh + (k * 16 + cq * 4 + cc) * 16);
#pragma unroll
                for (int q = 0; q < 4; q++) {
                    ulonglong2 b = br[q];
                    acc[2*q]   = ffma2(p2, b.x, acc[2*q]);
                    acc[2*q+1] = ffma2(p2, b.y, acc[2*q+1]);
                }
            }
        }
    }
    float* yo = y3d + (size_t)row * 16;
    float* mo = mix + (size_t)row * 80;
    __nv_bfloat16* mh = mixh + (size_t)row * 80;
    __nv_bfloat16* ml = mixl + (size_t)row * 80;
#pragma unroll
    for (int p = 0; p < 8; p++) {
        float2 v = unpack2(acc[p]);
        int j = 2 * p;
        float v0 = fmaxf(v.x * __ldg(gamma + j)     + __ldg(beta + j),     0.f);
        float v1 = fmaxf(v.y * __ldg(gamma + j + 1) + __ldg(beta + j + 1), 0.f);
        float2 o = make_float2(v0, v1);
        *(float2*)(yo + j) = o;
        *(float2*)(mo + j) = o;
        __nv_bfloat16 h0, l0, h1, l1;
        split_bf16(v0, h0, l0);
        split_bf16(v1, h1, l1);
        mh[j] = h0; mh[j+1] = h1;
        ml[j] = l0; ml[j+1] = l1;
    }
}

// =====================================================================
// FUSED dual-gate kernel: computes BOTH
//   p2d = (relu(y3d@Wg+bg) * f2g) @ Wp   (bf16 hi/lo out)
//   c2d = (relu(y3d@Wc+bc) * f2g) @ Wp   (fp32 out)
// sharing the f2g load and the Wp SMEM row between both projections.
// 256 thr: thread = (row r = tid>>1, col-half = tid&1, 32 cols each).
// =====================================================================
#define G2_WSG  0
#define G2_WSC  4144
#define G2_BG   8288
#define G2_BC   8548
#define G2_WP   8808
#define GATE2_FLOATS (G2_WP + 16576)   // 25384 floats = 101536 B

__global__ void __launch_bounds__(256)
gate2_kernel(const float* __restrict__ y3d, const float* __restrict__ f2d,
             const int* __restrict__ nn_idx,
             const float* __restrict__ Wg, const float* __restrict__ bg,
             const float* __restrict__ Wc, const float* __restrict__ bc,
             const float* __restrict__ Wp,
             __nv_bfloat16* __restrict__ p2h, __nv_bfloat16* __restrict__ p2l,
             float* __restrict__ c2d, int n)
{
    extern __shared__ float sh[];
    float* WsG = sh + G2_WSG;   // [259][16]
    float* WsC = sh + G2_WSC;   // [259][16]
    float* bG  = sh + G2_BG;    // [259]
    float* bC  = sh + G2_BC;    // [259]
    float* Wps = sh + G2_WP;    // [259][64]

    for (int t = threadIdx.x; t < 259 * 16; t += 256) {
        int c = t / 259, j = t - c * 259;
        WsG[j * 16 + c] = Wg[t];
        WsC[j * 16 + c] = Wc[t];
    }
    for (int t = threadIdx.x; t < 259; t += 256) { bG[t] = bg[t]; bC[t] = bc[t]; }
    for (int t = threadIdx.x; t < 259 * 16; t += 256)
        ((float4*)Wps)[t] = ((const float4*)Wp)[t];
    __syncthreads();

    const int r    = threadIdx.x >> 1;
    const int half = threadIdx.x & 1;
    const int row  = blockIdx.x * 128 + r;
    if (row >= n) return;
    const int jb = half * 32;

    ull accp[16], accc[16];
#pragma unroll
    for (int p = 0; p < 16; p++) { accp[p] = 0ull; accc[p] = 0ull; }

    int fi = nn_idx[row];
    if (fi >= 0) {
        ull y2[8];
#pragma unroll
        for (int cq = 0; cq < 4; cq++) {
            float4 v = *(const float4*)(y3d + (size_t)row * 16 + 4 * cq);
            y2[2*cq]   = packf2(v.x, v.y);
            y2[2*cq+1] = packf2(v.z, v.w);
        }
        const float* fr = f2d + (size_t)fi * 259;
#pragma unroll 2
        for (int j = 0; j < 259; j++) {
            const ulonglong2* wg = (const ulonglong2*)(WsG + j * 16);
            const ulonglong2* wc = (const ulonglong2*)(WsC + j * 16);
            ull dg = 0ull, dc = 0ull;
#pragma unroll
            for (int q = 0; q < 4; q++) {
                ulonglong2 a = wg[q];
                dg = ffma2(y2[2*q],   a.x, dg);
                dg = ffma2(y2[2*q+1], a.y, dg);
                ulonglong2 b = wc[q];
                dc = ffma2(y2[2*q],   b.x, dc);
                dc = ffma2(y2[2*q+1], b.y, dc);
            }
            float f = __ldg(fr + j);
            float2 g2 = unpack2(dg);
            float2 c2 = unpack2(dc);
            float sg = fmaxf(g2.x + g2.y + bG[j], 0.f) * f;
            float sc = fmaxf(c2.x + c2.y + bC[j], 0.f) * f;
            ull sg2 = pack2(sg), sc2 = pack2(sc);
            const ulonglong2* wp = (const ulonglong2*)(Wps + j * 64 + jb);
#pragma unroll
            for (int q = 0; q < 8; q++) {
                ulonglong2 w = wp[q];
                accp[2*q]   = ffma2(sg2, w.x, accp[2*q]);
                accp[2*q+1] = ffma2(sg2, w.y, accp[2*q+1]);
                accc[2*q]   = ffma2(sc2, w.x, accc[2*q]);
                accc[2*q+1] = ffma2(sc2, w.y, accc[2*q+1]);
            }
        }
    }
    // outputs
    __nv_bfloat16* oh = p2h + (size_t)row * 64 + jb;
    __nv_bfloat16* ol = p2l + (size_t)row * 64 + jb;
#pragma unroll
    for (int i = 0; i < 16; i++) {
        float2 v = unpack2(accp[i]);
        __nv_bfloat16 h0, l0, h1, l1;
        split_bf16(v.x, h0, l0);
        split_bf16(v.y, h1, l1);
        *(__nv_bfloat162*)(oh + 2*i) = __nv_bfloat162(h0, h1);
        *(__nv_bfloat162*)(ol + 2*i) = __nv_bfloat162(l0, l1);
    }
    float* oc = c2d + (size_t)row * 64 + jb;
#pragma unroll
    for (int q = 0; q < 8; q++) {
        float2 a = unpack2(accc[2*q]);
        float2 b = unpack2(accc[2*q+1]);
        *(float4*)(oc + 4*q) = make_float4(a.x, a.y, b.x, b.y);
    }
}

// =====================================================================
// WMMA conv (R12-proven): bf16x3 split, fp32 acc, mma.sync m16n16k16.
// Block = 128 thr / 4 warps / 128 rows (NPTS = 625*128, no tail).
// Per offset k: stage gathered hi/lo rows + weight slice into padded
// SMEM (stride CIN+8: conflict-free ldmatrix); each warp computes
// 2 m-tiles x NT n-tiles; 3 mmas per tile-pair (hh, hl, lh).
// EPI 0: relu(v*g+b)  EPI 1: relu(v*g+b)+res  EPI 2: relu(v*g+b+res)
// =====================================================================
template <int CIN, int COUT, int EPI>
__global__ void __launch_bounds__(128)
wmmaconv_kernel(const __nv_bfloat16* __restrict__ fh,
                const __nv_bfloat16* __restrict__ fl,
                const int* __restrict__ nbr,
                const __nv_bfloat16* __restrict__ wh,
                const __nv_bfloat16* __restrict__ wl,
                const float* __restrict__ gamma, const float* __restrict__ beta,
                const float* __restrict__ res, int resStride, int resCol0,
                float* __restrict__ outF, int ofStride, int ofCol0,
                __nv_bfloat16* __restrict__ outH, __nv_bfloat16* __restrict__ outL,
                int obStride, int obCol0)
{
    constexpr int KT  = CIN / 16;
    constexpr int NT  = COUT / 16;
    constexpr int SP  = CIN + 8;        // bf16 stride (conflict-free ldsm)
    constexpr int NCH = CIN / 8;        // 16B chunks per row
    constexpr int CP  = COUT + 4;       // fp32 epilogue stride

    extern __shared__ char sm[];
    __nv_bfloat16* Fh = (__nv_bfloat16*)sm;          // [128][SP]
    __nv_bfloat16* Fl = Fh + 128 * SP;               // [128][SP]
    __nv_bfloat16* Wh = Fl + 128 * SP;               // [COUT][SP]
    __nv_bfloat16* Wl = Wh + COUT * SP;              // [COUT][SP]

    const int tid  = threadIdx.x;
    const int warp = tid >> 5;
    const int rowbase = blockIdx.x * 128;
    const int m0 = warp * 32;

    wmma::fragment<wmma::accumulator, 16, 16, 16, float> acc[2][NT];
#pragma unroll
    for (int m = 0; m < 2; m++)
#pragma unroll
        for (int n = 0; n < NT; n++) wmma::fill_fragment(acc[m][n], 0.f);

    for (int k = 0; k < KOFF; k++) {
        __syncthreads();   // previous compute done reading F/W
        // ---- stage gathered features (hi/lo) ----
        for (int e = tid; e < 128 * NCH; e += 128) {
            int r = e / NCH, c = e - r * NCH;
            int idx = __ldg(nbr + (size_t)(rowbase + r) * KOFF + k);
            uint4 vh = make_uint4(0, 0, 0, 0), vl = vh;
            if (idx >= 0) {
                const char* ph = (const char*)(fh + (size_t)idx * CIN) + c * 16;
                const char* pl = (const char*)(fl + (size_t)idx * CIN) + c * 16;
                vh = *(const uint4*)ph;
                vl = *(const uint4*)pl;
            }
            *(uint4*)((char*)(Fh + r * SP) + c * 16) = vh;
            *(uint4*)((char*)(Fl + r * SP) + c * 16) = vl;
        }
        // ---- stage weights [COUT][CIN] hi/lo ----
        {
            const char* whk = (const char*)(wh + (size_t)k * COUT * CIN);
            const char* wlk = (const char*)(wl + (size_t)k * COUT * CIN);
            for (int e = tid; e < COUT * NCH; e += 128) {
                int r = e / NCH, c = e - r * NCH;
                uint4 vh = *(const uint4*)(whk + (size_t)r * CIN * 2 + c * 16);
                uint4 vl = *(const uint4*)(wlk + (size_t)r * CIN * 2 + c * 16);
                *(uint4*)((char*)(Wh + r * SP) + c * 16) = vh;
                *(uint4*)((char*)(Wl + r * SP) + c * 16) = vl;
            }
        }
        __syncthreads();

        // ---- compute ----
#pragma unroll
        for (int kk = 0; kk < KT; kk++) {
            wmma::fragment<wmma::matrix_a, 16, 16, 16, __nv_bfloat16,
                           wmma::row_major> Ah[2], Al[2];
#pragma unroll
            for (int m = 0; m < 2; m++) {
                wmma::load_matrix_sync(Ah[m], Fh + (m0 + m * 16) * SP + kk * 16, SP);
                wmma::load_matrix_sync(Al[m], Fl + (m0 + m * 16) * SP + kk * 16, SP);
            }
#pragma unroll
            for (int n = 0; n < NT; n++) {
                wmma::fragment<wmma::matrix_b, 16, 16, 16, __nv_bfloat16,
                               wmma::col_major> Bh, Bl;
                wmma::load_matrix_sync(Bh, Wh + (n * 16) * SP + kk * 16, SP);
                wmma::load_matrix_sync(Bl, Wl + (n * 16) * SP + kk * 16, SP);
#pragma unroll
                for (int m = 0; m < 2; m++) {
                    wmma::mma_sync(acc[m][n], Ah[m], Bh, acc[m][n]);
                    wmma::mma_sync(acc[m][n], Ah[m], Bl, acc[m][n]);
                    wmma::mma_sync(acc[m][n], Al[m], Bh, acc[m][n]);
                }
            }
        }
    }

    // ---- epilogue: frags -> SMEM fp32, then fused bn/relu/residual ----
    __syncthreads();
    float* C = (float*)sm;   // [128][CP] (fits inside staged-tile region)
#pragma unroll
    for (int m = 0; m < 2; m++)
#pragma unroll
        for (int n = 0; n < NT; n++)
            wmma::store_matrix_sync(C + (m0 + m * 16) * CP + n * 16,
                                    acc[m][n], CP, wmma::mem_row_major);
    __syncthreads();

    for (int e = tid; e < 128 * COUT; e += 128) {
        int r = e / COUT, j = e - r * COUT;
        int row = rowbase + r;
        float v = C[r * CP + j] * __ldg(gamma + j) + __ldg(beta + j);
        float rv = 0.f;
        if (EPI != 0) rv = res[(size_t)row * resStride + resCol0 + j];
        if (EPI == 2) v += rv;
        v = fmaxf(v, 0.f);
        if (EPI == 1) v += rv;
        if (outF) outF[(size_t)row * ofStride + ofCol0 + j] = v;
        if (outH) {
            __nv_bfloat16 h, l;
            split_bf16(v, h, l);
            outH[(size_t)row * obStride + obCol0 + j] = h;
            outL[(size_t)row * obStride + obCol0 + j] = l;
        }
    }
}

// =====================================================================
// SIMT conv (downsample layer only): CIN=80 -> COUT=96
// =====================================================================
template <int CIN, int COUT, int EPI>
__global__ void __launch_bounds__(256)
conv3_kernel(const float* __restrict__ feats, const int* __restrict__ nbr,
             const float* __restrict__ W, const float* __restrict__ gamma,
             const float* __restrict__ beta, const float* __restrict__ res,
             float* __restrict__ out, int n_out, int out_stride, int out_col0)
{
    constexpr int TN   = COUT / 4;
    constexpr int NV   = CIN / 4;
    constexpr int CPAD = (CIN == 64) ? 68 : 84;
    constexpr int WSZ  = CIN * COUT;

    extern __shared__ float smf[];
    float* F  = smf;
    float* Wb = smf + 128 * CPAD;

    const int tid  = threadIdx.x;
    const int warp = tid >> 5, lane = tid & 31;
    const int ng = lane >> 3, rg = lane & 7;
    const int jb = ng * TN;
    const int rowbase = blockIdx.x * 128;
    const int rl0 = warp * 16 + rg;

    ull acc[2][TN / 2];
#pragma unroll
    for (int r = 0; r < 2; r++)
#pragma unroll
        for (int p = 0; p < TN / 2; p++) acc[r][p] = 0ull;

    for (int k = 0; k < KOFF; k++) {
        __syncthreads();
        {
            const float4* src = (const float4*)(W + (size_t)k * WSZ);
            float4* dst = (float4*)Wb;
            for (int t = tid; t < WSZ / 4; t += 256) dst[t] = src[t];
        }
        for (int e = tid; e < 128 * NV; e += 256) {
            int r  = e / NV;
            int c4 = e - r * NV;
            int grow = rowbase + r;
            float4 v = make_float4(0.f, 0.f, 0.f, 0.f);
            if (grow < n_out) {
                int idx = __ldg(nbr + (size_t)grow * KOFF + k);
                if (idx >= 0)
                    v = *(const float4*)(feats + (size_t)idx * CIN + 4 * c4);
            }
            *(float4*)(F + r * CPAD + 4 * c4) = v;
        }
        __syncthreads();

        const float* F0 = F + rl0 * CPAD;
        const float* F1 = F0 + 8 * CPAD;
#pragma unroll
        for (int cq = 0; cq < NV; cq++) {
            float4 a0 = *(const float4*)(F0 + 4 * cq);
            float4 a1 = *(const float4*)(F1 + 4 * cq);
#pragma unroll
            for (int cc = 0; cc < 4; cc++) {
                float v0 = (cc == 0) ? a0.x : (cc == 1) ? a0.y : (cc == 2) ? a0.z : a0.w;
                float v1 = (cc == 0) ? a1.x : (cc == 1) ? a1.y : (cc == 2) ? a1.z : a1.w;
                ull p0 = pack2(v0), p1 = pack2(v1);
                const ulonglong2* br =
                    (const ulonglong2*)(Wb + (cq * 4 + cc) * COUT + jb);
#pragma unroll
                for (int q = 0; q < TN / 4; q++) {
                    ulonglong2 b = br[q];
                    acc[0][2*q]   = ffma2(p0, b.x, acc[0][2*q]);
                    acc[0][2*q+1] = ffma2(p0, b.y, acc[0][2*q+1]);
                    acc[1][2*q]   = ffma2(p1, b.x, acc[1][2*q]);
                    acc[1][2*q+1] = ffma2(p1, b.y, acc[1][2*q+1]);
                }
            }
        }
    }

#pragma unroll
    for (int r = 0; r < 2; r++) {
        int row = rowbase + rl0 + 8 * r;
        if (row >= n_out) continue;
        float* o = out + (size_t)row * out_stride + out_col0 + jb;
        const float* rr = (EPI != 0) ? (res + (size_t)row * COUT + jb) : nullptr;
#pragma unroll
        for (int p = 0; p < TN / 2; p++) {
            float2 v = unpack2(acc[r][p]);
            int j = jb + 2 * p;
            float x0 = v.x * __ldg(gamma + j)     + __ldg(beta + j);
            float x1 = v.y * __ldg(gamma + j + 1) + __ldg(beta + j + 1);
            float r0v = 0.f, r1v = 0.f;
            if (EPI != 0) { r0v = rr[2*p]; r1v = rr[2*p + 1]; }
            if (EPI == 2) { x0 += r0v; x1 += r1v; }
            x0 = fmaxf(x0, 0.f);
            x1 = fmaxf(x1, 0.f);
            if (EPI == 1) { x0 += r0v; x1 += r1v; }
            *(float2*)(o + 2 * p) = make_float2(x0, x1);
        }
    }
}

#define SMEM_C96   ((128 * 84 + 80 * 96) * 4)
// wmma smem: (2*128*SP + 2*COUT*SP) bf16 ; epilogue needs 128*CP*4 (smaller)
#define SMEM_W64   ((2 * 128 * 72 + 2 * 64 * 72) * 2)   // 55296
#define SMEM_W80   ((2 * 128 * 88 + 2 * 80 * 88) * 2)   // 73216

// =====================================================================
// Launch
// =====================================================================
extern "C" void kernel_launch(void* const* d_in, const int* in_sizes, int n_in,
                              void* d_out, int out_size)
{
    const float* x3d    = (const float*)d_in[0];
    const float* f2d    = (const float*)d_in[1];
    const int*   nn_idx = (const int*)  d_in[2];
    const int*   nbr    = (const int*)  d_in[3];
    const int*   nbr_ds = (const int*)  d_in[4];
    const float* W3d    = (const float*)d_in[5];
    const float* g3d    = (const float*)d_in[6];
    const float* b3d    = (const float*)d_in[7];
    const float* Wg     = (const float*)d_in[8];
    const float* bg     = (const float*)d_in[9];
    const float* Wc     = (const float*)d_in[10];
    const float* bc     = (const float*)d_in[11];
    const float* Wp     = (const float*)d_in[12];
    const float* W2d    = (const float*)d_in[13];
    const float* g2d    = (const float*)d_in[14];
    const float* b2d    = (const float*)d_in[15];
    const float* Wm1    = (const float*)d_in[16];
    const float* gm1    = (const float*)d_in[17];
    const float* bm1    = (const float*)d_in[18];
    const float* Wm2    = (const float*)d_in[19];
    const float* gm2    = (const float*)d_in[20];
    const float* bm2    = (const float*)d_in[21];
    const float* Wa1    = (const float*)d_in[22];
    const float* ga1    = (const float*)d_in[23];
    const float* ba1    = (const float*)d_in[24];
    const float* Wa2    = (const float*)d_in[25];
    const float* ga2    = (const float*)d_in[26];
    const float* ba2    = (const float*)d_in[27];
    const float* Wds    = (const float*)d_in[28];
    const float* gds    = (const float*)d_in[29];
    const float* bds    = (const float*)d_in[30];
    float* out = (float*)d_out;

    float *y3d, *c2d, *mix, *hbuf, *abuf;
    cudaGetSymbolAddress((void**)&y3d,  g_y3d);
    cudaGetSymbolAddress((void**)&c2d,  g_c2d);
    cudaGetSymbolAddress((void**)&mix,  g_mix);
    cudaGetSymbolAddress((void**)&hbuf, g_h);
    cudaGetSymbolAddress((void**)&abuf, g_a);

    __nv_bfloat16 *p2h, *p2l, *mixh, *mixl, *th, *tl, *hh, *hl;
    cudaGetSymbolAddress((void**)&p2h,  g_p2h);
    cudaGetSymbolAddress((void**)&p2l,  g_p2l);
    cudaGetSymbolAddress((void**)&mixh, g_mixh);
    cudaGetSymbolAddress((void**)&mixl, g_mixl);
    cudaGetSymbolAddress((void**)&th,   g_th);
    cudaGetSymbolAddress((void**)&tl,   g_tl);
    cudaGetSymbolAddress((void**)&hh,   g_hh);
    cudaGetSymbolAddress((void**)&hl,   g_hl);

    __nv_bfloat16 *w2h, *w2l, *wm1h, *wm1l, *wm2h, *wm2l, *wa1h, *wa1l, *wa2h, *wa2l;
    cudaGetSymbolAddress((void**)&w2h,  g_w2h);
    cudaGetSymbolAddress((void**)&w2l,  g_w2l);
    cudaGetSymbolAddress((void**)&wm1h, g_wm1h);
    cudaGetSymbolAddress((void**)&wm1l, g_wm1l);
    cudaGetSymbolAddress((void**)&wm2h, g_wm2h);
    cudaGetSymbolAddress((void**)&wm2l, g_wm2l);
    cudaGetSymbolAddress((void**)&wa1h, g_wa1h);
    cudaGetSymbolAddress((void**)&wa1l, g_wa1l);
    cudaGetSymbolAddress((void**)&wa2h, g_wa2h);
    cudaGetSymbolAddress((void**)&wa2l, g_wa2l);

    cudaFuncSetAttribute(gate2_kernel, cudaFuncAttributeMaxDynamicSharedMemorySize,
                         GATE2_FLOATS * (int)sizeof(float));
    cudaFuncSetAttribute(wmmaconv_kernel<64, 64, 1>,
                         cudaFuncAttributeMaxDynamicSharedMemorySize, SMEM_W64);
    cudaFuncSetAttribute(wmmaconv_kernel<80, 80, 0>,
                         cudaFuncAttributeMaxDynamicSharedMemorySize, SMEM_W80);
    cudaFuncSetAttribute(wmmaconv_kernel<80, 80, 2>,
                         cudaFuncAttributeMaxDynamicSharedMemorySize, SMEM_W80);
    cudaFuncSetAttribute(conv3_kernel<80, 96, 0>,
                         cudaFuncAttributeMaxDynamicSharedMemorySize, SMEM_C96);

    const int B256 = (NPTS + 255) / 256;
    const int BC   = NPTS / 128;           // 625 (exact)
    const int BG   = (NPTS + 127) / 128;   // 625 (gate2: 128 rows/block)
    const int BDS  = (NDPTS + 127) / 128;  // 79

    // 0. weight transpose + bf16 split
    prep_w<<<(KOFF*64*64 + 255)/256, 256>>>(W2d, w2h, w2l, 64, 64);
    prep_w<<<(KOFF*80*80 + 255)/256, 256>>>(Wm1, wm1h, wm1l, 80, 80);
    prep_w<<<(KOFF*80*80 + 255)/256, 256>>>(Wm2, wm2h, wm2l, 80, 80);
    prep_w<<<(KOFF*80*80 + 255)/256, 256>>>(Wa1, wa1h, wa1l, 80, 80);
    prep_w<<<(KOFF*80*80 + 255)/256, 256>>>(Wa2, wa2h, wa2l, 80, 80);

    // 1. y3d + mix[:,0:16]
    conv16_kernel<<<B256, 256>>>(x3d, nbr, W3d, g3d, b3d, y3d, mix, mixh, mixl, NPTS);

    // 2. fused dual gate: p2d (bf16 hi/lo) + c2d (fp32) in one pass
    gate2_kernel<<<BG, 256, GATE2_FLOATS * sizeof(float)>>>(
        y3d, f2d, nn_idx, Wg, bg, Wc, bc, Wp, p2h, p2l, c2d, NPTS);

    // 3. mix[:,16:80] = bn_relu(conv64(p2d)) + c2d
    wmmaconv_kernel<64, 64, 1><<<BC, 128, SMEM_W64>>>(
        p2h, p2l, nbr, w2h, w2l, g2d, b2d,
        c2d, 64, 0, mix, 80, 16, mixh, mixl, 80, 16);

    // 4. t = bn_relu(conv80(mix, Wm1))  (bf16 only)
    wmmaconv_kernel<80, 80, 0><<<BC, 128, SMEM_W80>>>(
        mixh, mixl, nbr, wm1h, wm1l, gm1, bm1,
        nullptr, 0, 0, nullptr, 0, 0, th, tl, 80, 0);

    // 5. h = relu(conv80(t, Wm2)*g + b + mix)  (fp32 + bf16)
    wmmaconv_kernel<80, 80, 2><<<BC, 128, SMEM_W80>>>(
        th, tl, nbr, wm2h, wm2l, gm2, bm2,
        mix, 80, 0, hbuf, 80, 0, hh, hl, 80, 0);

    // 6. t = bn_relu(conv80(h, Wa1))  (bf16 only)
    wmmaconv_kernel<80, 80, 0><<<BC, 128, SMEM_W80>>>(
        hh, hl, nbr, wa1h, wa1l, ga1, ba1,
        nullptr, 0, 0, nullptr, 0, 0, th, tl, 80, 0);

    // 7. a = relu(conv80(t, Wa2)*g + b + h)  (fp32 only)
    wmmaconv_kernel<80, 80, 2><<<BC, 128, SMEM_W80>>>(
        th, tl, nbr, wa2h, wa2l, ga2, ba2,
        hbuf, 80, 0, abuf, 80, 0, nullptr, nullptr, 80, 0);

    // 8. out = bn_relu(conv80->96(a, nbr_ds, Wds))  (SIMT)
    conv3_kernel<80, 96, 0><<<BDS, 256, SMEM_C96>>>(
        abuf, nbr_ds, Wds, gds, bds, nullptr, out, NDPTS, 96, 0);
}